// round 2
// baseline (speedup 1.0000x reference)
#include <cuda_runtime.h>
#include <cuda_bf16.h>
#include <math.h>

#define NMAX 50000
#define EMAX 800000
#define GMAX 500
#define HID  64

// ---------------- device scratch (static, no runtime allocation) ----------
__device__ int   g_is64;             // 1 if index tensors are int64, 0 if int32
__device__ int   g_deg[NMAX];        // in-degree + 1 (self loop)
__device__ int   g_fill[NMAX];       // fill cursors for CSR build
__device__ float g_dis[NMAX];        // rsqrt(deg)
__device__ int   g_rowptr[NMAX + 1]; // CSR row offsets (edges only)
__device__ int   g_col[EMAX];        // CSR column (src node) per edge
__device__ float g_wgt[EMAX];        // dis[src]*dis[dst] per edge
__device__ float g_bufA[NMAX * HID];
__device__ float g_bufB[NMAX * HID];
__device__ int   g_segstart[GMAX + 1];

// Branch on detected dtype. g_is64 is set before any consumer runs.
__device__ __forceinline__ int load_idx(const void* p, long long i) {
    if (g_is64) return (int)((const long long*)p)[i];
    return ((const int*)p)[i];
}

// ---------------- index dtype detection ------------------------------------
// If the buffer holds little-endian int64 values in [0, N), every odd 32-bit
// word is 0. For genuine int32 indices in [0, N) the odd words are themselves
// random indices, which are ~never all zero across 2048 samples.
__global__ void detect_kernel(const int* __restrict__ ei32) {
    __shared__ int acc[256];
    int t = threadIdx.x;
    int v = 0;
    for (int i = t; i < 2048; i += 256) v |= ei32[2 * i + 1];
    acc[t] = v;
    __syncthreads();
    for (int off = 128; off > 0; off >>= 1) {
        if (t < off) acc[t] |= acc[t + off];
        __syncthreads();
    }
    if (t == 0) g_is64 = (acc[0] == 0) ? 1 : 0;
}

// ---------------- CSR construction ----------------------------------------
__global__ void init_kernel(int n) {
    int i = blockIdx.x * blockDim.x + threadIdx.x;
    if (i < n) { g_deg[i] = 1; g_fill[i] = 0; }
}

__global__ void deg_kernel(const void* __restrict__ ei, int e) {
    int i = blockIdx.x * blockDim.x + threadIdx.x;
    if (i < e) {
        int d = load_idx(ei, (long long)e + i);  // dst row of edge_index
        atomicAdd(&g_deg[d], 1);
    }
}

__global__ void dis_kernel(int n) {
    int i = blockIdx.x * blockDim.x + threadIdx.x;
    if (i < n) g_dis[i] = rsqrtf((float)g_deg[i]);
}

// Single-block exclusive prefix sum over (deg[i]-1) -> rowptr.
__global__ void scan_kernel(int n, int e_total) {
    __shared__ int sh[1024];
    int t = threadIdx.x;
    int ch = (n + 1023) / 1024;
    int beg = t * ch;
    int end = min(beg + ch, n);
    int s = 0;
    for (int i = beg; i < end; ++i) s += g_deg[i] - 1;
    sh[t] = s;
    __syncthreads();
    for (int off = 1; off < 1024; off <<= 1) {
        int v = sh[t];
        int u = (t >= off) ? sh[t - off] : 0;
        __syncthreads();
        sh[t] = v + u;
        __syncthreads();
    }
    int excl = (t == 0) ? 0 : sh[t - 1];
    for (int i = beg; i < end; ++i) {
        g_rowptr[i] = excl;
        excl += g_deg[i] - 1;
    }
    if (t == 1023) g_rowptr[n] = e_total;
}

__global__ void fill_kernel(const void* __restrict__ ei, int e) {
    int i = blockIdx.x * blockDim.x + threadIdx.x;
    if (i >= e) return;
    int s = load_idx(ei, i);
    int d = load_idx(ei, (long long)e + i);
    int pos = g_rowptr[d] + atomicAdd(&g_fill[d], 1);
    g_col[pos] = s;
    g_wgt[pos] = g_dis[s] * g_dis[d];
}

// ---------------- dense 64x64 GEMM (out = in @ W), 2 threads per row ------
__global__ void gemm64_kernel(const float* __restrict__ in,
                              const float* __restrict__ W,
                              float* __restrict__ out, int n) {
    __shared__ float Ws[64 * 64];
    int tid = threadIdx.x;  // 256
#pragma unroll
    for (int i = 0; i < 16; ++i) Ws[tid + 256 * i] = W[tid + 256 * i];
    __syncthreads();

    int row  = blockIdx.x * 128 + (tid & 127);
    int half = tid >> 7;   // uniform per warp
    if (row >= n) return;

    float acc[32];
#pragma unroll
    for (int j = 0; j < 32; ++j) acc[j] = 0.f;

    const float4* xr = reinterpret_cast<const float4*>(in + row * 64);
    const float*  wb = Ws + half * 32;

#pragma unroll 2
    for (int k4 = 0; k4 < 16; ++k4) {
        float4 xv = xr[k4];
        float xk[4] = {xv.x, xv.y, xv.z, xv.w};
#pragma unroll
        for (int kk = 0; kk < 4; ++kk) {
            const float4* wrow =
                reinterpret_cast<const float4*>(wb + (k4 * 4 + kk) * 64);
#pragma unroll
            for (int j4 = 0; j4 < 8; ++j4) {
                float4 wv = wrow[j4];
                acc[j4 * 4 + 0] += xk[kk] * wv.x;
                acc[j4 * 4 + 1] += xk[kk] * wv.y;
                acc[j4 * 4 + 2] += xk[kk] * wv.z;
                acc[j4 * 4 + 3] += xk[kk] * wv.w;
            }
        }
    }

    float4* o = reinterpret_cast<float4*>(out + row * 64 + half * 32);
#pragma unroll
    for (int j4 = 0; j4 < 8; ++j4)
        o[j4] = make_float4(acc[j4 * 4], acc[j4 * 4 + 1],
                            acc[j4 * 4 + 2], acc[j4 * 4 + 3]);
}

// ---------------- per-node aggregation + bias + relu (warp per node) ------
__global__ void agg_kernel(const float* __restrict__ t,
                           const float* __restrict__ bias,
                           float* __restrict__ out, int n) {
    int wid  = (blockIdx.x * blockDim.x + threadIdx.x) >> 5;
    int lane = threadIdx.x & 31;
    if (wid >= n) return;

    float d = g_dis[wid];
    float2 v0 = *reinterpret_cast<const float2*>(t + wid * 64 + lane * 2);
    float2 acc;
    acc.x = d * d * v0.x;  // self-loop term
    acc.y = d * d * v0.y;

    int beg = g_rowptr[wid];
    int end = g_rowptr[wid + 1];
    for (int e = beg; e < end; ++e) {
        int   s = g_col[e];
        float w = g_wgt[e];
        float2 v = *reinterpret_cast<const float2*>(t + s * 64 + lane * 2);
        acc.x += w * v.x;
        acc.y += w * v.y;
    }

    float2 b = *reinterpret_cast<const float2*>(bias + lane * 2);
    float2 r;
    r.x = fmaxf(acc.x + b.x, 0.f);
    r.y = fmaxf(acc.y + b.y, 0.f);
    *reinterpret_cast<float2*>(out + wid * 64 + lane * 2) = r;
}

// ---------------- segment boundaries from sorted batch --------------------
__global__ void seg_kernel(const void* __restrict__ batch, int n, int g_cnt) {
    int i = blockIdx.x * blockDim.x + threadIdx.x;
    if (i >= n) return;
    int b  = load_idx(batch, i);
    int bp = (i == 0) ? -1 : load_idx(batch, i - 1);
    for (int g = bp + 1; g <= b; ++g) g_segstart[g] = i;
    if (i == n - 1) {
        for (int g = b + 1; g <= g_cnt; ++g) g_segstart[g] = n;
    }
}

// ---------------- mean pool + MLP + log_softmax (block per graph) ---------
__global__ void pool_mlp_kernel(const float* __restrict__ h,
                                const float* __restrict__ lin1W,
                                const float* __restrict__ lin1b,
                                const float* __restrict__ lin2W,
                                const float* __restrict__ lin2b,
                                float* __restrict__ out) {
    int g   = blockIdx.x;
    int tid = threadIdx.x;  // 64
    __shared__ float pooled[64];
    __shared__ float h1[64];
    __shared__ float logits[10];
    __shared__ float lse;

    int beg = g_segstart[g];
    int end = g_segstart[g + 1];
    float s = 0.f;
    for (int r = beg; r < end; ++r) s += h[r * 64 + tid];
    int cnt = end - beg;
    pooled[tid] = s / (float)max(cnt, 1);
    __syncthreads();

    float a = lin1b[tid];
#pragma unroll
    for (int k = 0; k < 64; ++k) a += pooled[k] * lin1W[k * 64 + tid];
    h1[tid] = fmaxf(a, 0.f);
    __syncthreads();

    if (tid < 10) {
        float l = lin2b[tid];
#pragma unroll
        for (int k = 0; k < 64; ++k) l += h1[k] * lin2W[k * 10 + tid];
        logits[tid] = l;
    }
    __syncthreads();

    if (tid == 0) {
        float m = logits[0];
        for (int j = 1; j < 10; ++j) m = fmaxf(m, logits[j]);
        float se = 0.f;
        for (int j = 0; j < 10; ++j) se += expf(logits[j] - m);
        lse = m + logf(se);
    }
    __syncthreads();

    if (tid < 10) out[g * 10 + tid] = logits[tid] - lse;
}

// ---------------- launch ---------------------------------------------------
extern "C" void kernel_launch(void* const* d_in, const int* in_sizes, int n_in,
                              void* d_out, int out_size) {
    const float* x     = (const float*)d_in[0];
    const void*  ei    = d_in[1];
    const void*  batch = d_in[2];
    const float* W1 = (const float*)d_in[3];
    const float* b1 = (const float*)d_in[4];
    const float* W2 = (const float*)d_in[5];
    const float* b2 = (const float*)d_in[6];
    const float* W3 = (const float*)d_in[7];
    const float* b3 = (const float*)d_in[8];
    const float* l1W = (const float*)d_in[9];
    const float* l1b = (const float*)d_in[10];
    const float* l2W = (const float*)d_in[11];
    const float* l2b = (const float*)d_in[12];
    float* out = (float*)d_out;

    const int n = in_sizes[0] / HID;
    const int e = in_sizes[1] / 2;
    const int G = out_size / 10;

    float* bufA = nullptr;
    float* bufB = nullptr;
    cudaGetSymbolAddress((void**)&bufA, g_bufA);
    cudaGetSymbolAddress((void**)&bufB, g_bufB);

    int tpb = 256;
    // dtype detection first — everything downstream branches on g_is64
    detect_kernel<<<1, 256>>>((const int*)ei);
    // CSR build
    init_kernel<<<(n + tpb - 1) / tpb, tpb>>>(n);
    deg_kernel<<<(e + tpb - 1) / tpb, tpb>>>(ei, e);
    dis_kernel<<<(n + tpb - 1) / tpb, tpb>>>(n);
    scan_kernel<<<1, 1024>>>(n, e);
    fill_kernel<<<(e + tpb - 1) / tpb, tpb>>>(ei, e);

    int gemm_blocks = (n + 127) / 128;
    int agg_blocks  = (n * 32 + tpb - 1) / tpb;

    gemm64_kernel<<<gemm_blocks, 256>>>(x, W1, bufB, n);
    agg_kernel<<<agg_blocks, tpb>>>(bufB, b1, bufA, n);
    gemm64_kernel<<<gemm_blocks, 256>>>(bufA, W2, bufB, n);
    agg_kernel<<<agg_blocks, tpb>>>(bufB, b2, bufA, n);
    gemm64_kernel<<<gemm_blocks, 256>>>(bufA, W3, bufB, n);
    agg_kernel<<<agg_blocks, tpb>>>(bufB, b3, bufA, n);

    seg_kernel<<<(n + tpb - 1) / tpb, tpb>>>(batch, n, G);
    pool_mlp_kernel<<<G, 64>>>(bufA, l1W, l1b, l2W, l2b, out);
}